// round 9
// baseline (speedup 1.0000x reference)
#include <cuda_runtime.h>
#include <math.h>
#include <stdint.h>

#ifndef M_PI
#define M_PI 3.14159265358979323846
#endif

// Problem shape (fixed by setup_inputs)
#define BB 2
#define NV 4
#define HH 256
#define WW 512
#define HWSZ (HH * WW)            // 131072
#define PP (NV * HWSZ)            // 524288 points per batch
#define TOTAL (BB * PP)           // 1048576 points total
#define NCH 24

#define VOXEL_SIZE 0.1f
#define CONF_W 0.7f
#define OPAC_W 0.3f
#define CONF_THRESH 0.1f
#define OPAC_THRESH 0.01f

#define TABLE_BITS 21
#define TABLE_SIZE (1u << TABLE_BITS)
#define TABLE_MASK (TABLE_SIZE - 1u)
#define INV_SLOT 0xFFFFFFFFu

// Scratch (no runtime allocation -> __device__ globals, ZERO-INITIALIZED at
// module load; the cleanup kernel restores the zero state after every launch,
// so each graph replay starts clean). Empty key encoding is 0; real keys
// always have bit 31 set.
__device__ unsigned int  g_keys[TABLE_SIZE];        // 8 MB, 0 = empty
__device__ ulonglong2    g_pair[TABLE_SIZE];        // 32 MB: {max1, max2}
__device__ unsigned int  g_slot[TOTAL];             // 4 MB
__device__ unsigned int  g_used[TOTAL];             // claimed slot list
__device__ unsigned int  g_cnt;                     // #claimed slots
__device__ unsigned int  g_done;                    // cleanup block counter

// ---------------------------------------------------------------------------

// Find (or claim) the table slot for voxel `key` (key != 0 guaranteed).
// On first claim of a slot, record it for post-run cleanup.
__device__ __forceinline__ unsigned probe_slot(unsigned key) {
    unsigned h = (key * 2654435761u) >> (32 - TABLE_BITS);
    for (;;) {
        unsigned cur = g_keys[h];
        if (cur == key) return h;
        if (cur == 0u) {
            unsigned prev = atomicCAS(&g_keys[h], 0u, key);
            if (prev == 0u) {                       // we claimed it: record
                unsigned idx = atomicAdd(&g_cnt, 1u);
                g_used[idx] = h;
                return h;
            }
            if (prev == key) return h;
        }
        h = (h + 1u) & TABLE_MASK;
    }
}

// Packed (score, index) key — ONE definition so pass1/pass3 agree bit-exactly.
__device__ __forceinline__ unsigned long long pack_key(float c, float o,
                                                       unsigned p) {
    float score = __fmaf_rn(CONF_W, c, __fmul_rn(OPAC_W, o));
    return ((unsigned long long)__float_as_uint(score) << 32)
         | (unsigned long long)(0xFFFFFFFFu - p);
}

// Identical arithmetic to the R6 passing kernel (proven numerics).
__device__ __forceinline__ void compute_point(
    int g, const float* __restrict__ depth, const float* __restrict__ opac,
    const float* __restrict__ conf, const float* __restrict__ poses,
    bool& valid, unsigned& key, unsigned long long& packed,
    float& mx, float& my, float& mz)
{
    int b  = g / PP;
    int p  = g - b * PP;
    int n  = p / HWSZ;
    int hw = p - n * HWSZ;
    int h  = hw / WW;
    int w  = hw - h * WW;

    float d = depth[g];
    float c = conf[g];
    float o = opac[g];
    valid = (c > CONF_THRESH) && (o > OPAC_THRESH);

    const float fx = (float)((double)WW / (2.0 * M_PI));
    const float fy = (float)(-(double)HH / M_PI);
    float lon = ((float)w + 0.5f - (float)(WW / 2)) / fx;
    float lat = ((float)h + 0.5f - (float)(HH / 2)) / fy;
    float slat, clat, slon, clon;
    sincosf(lat, &slat, &clat);
    sincosf(lon, &slon, &clon);
    float dx = clat * slon;
    float dy = -slat;
    float dz = clat * clon;

    float px = d * dx, py = d * dy, pz = d * dz;

    const float* M = poses + (size_t)(b * NV + n) * 16;
    mx = M[0] * px + M[1] * py + M[2]  * pz + M[3];
    my = M[4] * px + M[5] * py + M[6]  * pz + M[7];
    mz = M[8] * px + M[9] * py + M[10] * pz + M[11];

    int vx = min(max((int)floorf(mx / VOXEL_SIZE) + 512, 0), 1023);
    int vy = min(max((int)floorf(my / VOXEL_SIZE) + 512, 0), 1023);
    int vz = min(max((int)floorf(mz / VOXEL_SIZE) + 512, 0), 1023);
    unsigned vid = ((unsigned)vx << 20) | ((unsigned)vy << 10) | (unsigned)vz;
    // bit 31 forced -> key is never 0 (0 means empty slot)
    key = 0x80000000u | ((unsigned)b << 30) | vid;

    packed = pack_key(c, o, (unsigned)p);
}

// Streaming top-2: one atomicMax with return + one fire-and-forget RED.MAX.
// (R6 proven form: no warp aggregation — atomics are not the bottleneck.)
__global__ void __launch_bounds__(256) pass1_kernel(
    const float* __restrict__ depth, const float* __restrict__ opac,
    const float* __restrict__ conf,  const float* __restrict__ poses)
{
    int g = blockIdx.x * blockDim.x + threadIdx.x;
    if (g >= TOTAL) return;

    bool valid; unsigned key; unsigned long long pk;
    float mx, my, mz;
    compute_point(g, depth, opac, conf, poses, valid, key, pk, mx, my, mz);

    if (!valid) { g_slot[g] = INV_SLOT; return; }

    unsigned slot = probe_slot(key);
    unsigned long long* m1 =
        &reinterpret_cast<unsigned long long*>(g_pair)[2 * (size_t)slot];
    unsigned long long old = atomicMax(m1, pk);
    unsigned long long v = (pk < old) ? pk : old;   // displaced value
    if (v != 0ull)
        atomicMax(m1 + 1, v);                       // result unused -> RED

    g_slot[g] = slot;
}

__global__ void __launch_bounds__(256) pass3_kernel(
    const float* __restrict__ depth, const float* __restrict__ cov,
    const float* __restrict__ rot,   const float* __restrict__ opac,
    const float* __restrict__ sh,    const float* __restrict__ conf,
    const float* __restrict__ poses, float* __restrict__ out,
    int write_sel, size_t sel_off)
{
    int g = blockIdx.x * blockDim.x + threadIdx.x;
    if (g >= TOTAL) return;

    bool valid; unsigned key; unsigned long long packed;
    float mx, my, mz;
    compute_point(g, depth, opac, conf, poses, valid, key, packed, mx, my, mz);

    float s = 0.0f;
    unsigned slot = g_slot[g];
    if (slot != INV_SLOT) {
        ulonglong2 pr = __ldg(&g_pair[slot]);       // one 16B read for both
        if (packed == pr.x || packed == pr.y) s = 1.0f;
    }

    int b  = g / PP;
    int p  = g - b * PP;
    int n  = p / HWSZ;
    int hw = p - n * HWSZ;

    size_t bn     = (size_t)(b * NV + n);
    size_t base_c = (bn * 3)  * HWSZ + hw;
    size_t base_r = (bn * 4)  * HWSZ + hw;
    size_t base_s = (bn * 12) * HWSZ + hw;

    float f[NCH];
    f[0] = mx; f[1] = my; f[2] = mz;
    f[3] = __ldcs(&cov[base_c]);
    f[4] = __ldcs(&cov[base_c + HWSZ]);
    f[5] = __ldcs(&cov[base_c + 2 * (size_t)HWSZ]);
#pragma unroll
    for (int i = 0; i < 4; i++)
        f[6 + i] = __ldcs(&rot[base_r + (size_t)i * HWSZ]);
    f[10] = opac[g];
#pragma unroll
    for (int i = 0; i < 12; i++)
        f[11 + i] = __ldcs(&sh[base_s + (size_t)i * HWSZ]);
    f[23] = conf[g];

#pragma unroll
    for (int i = 0; i < NCH; i++) f[i] *= s;

    float4* dst = reinterpret_cast<float4*>(out + (size_t)g * NCH);
#pragma unroll
    for (int i = 0; i < 6; i++)
        __stcs(dst + i, make_float4(f[4*i], f[4*i+1], f[4*i+2], f[4*i+3]));

    if (write_sel)
        __stcs(out + sel_off + (size_t)g, s);
}

// Zero only the slots that were claimed this launch; restores the pristine
// zero state so the next replay starts clean. Last block resets the counters.
#define CLEAN_BLOCKS 512
__global__ void __launch_bounds__(256) cleanup_kernel() {
    unsigned cnt = *(volatile unsigned*)&g_cnt;
    unsigned stride = CLEAN_BLOCKS * 256;
    for (unsigned i = blockIdx.x * 256 + threadIdx.x; i < cnt; i += stride) {
        unsigned slot = g_used[i];
        g_keys[slot] = 0u;
        ulonglong2 z; z.x = 0ull; z.y = 0ull;
        g_pair[slot] = z;
    }
    __threadfence();
    if (threadIdx.x == 0) {
        unsigned done = atomicAdd(&g_done, 1u);
        if (done == CLEAN_BLOCKS - 1) {
            g_cnt = 0u;
            g_done = 0u;
            __threadfence();
        }
    }
}

// ---------------------------------------------------------------------------

extern "C" void kernel_launch(void* const* d_in, const int* in_sizes, int n_in,
                              void* d_out, int out_size) {
    const float* depth = (const float*)d_in[0];
    const float* cov   = (const float*)d_in[1];
    const float* rot   = (const float*)d_in[2];
    const float* opac  = (const float*)d_in[3];
    const float* sh    = (const float*)d_in[4];
    const float* conf  = (const float*)d_in[5];
    const float* poses = (const float*)d_in[6];
    float* out = (float*)d_out;

    size_t featN = (size_t)TOTAL * NCH;
    int write_sel = ((size_t)out_size >= featN + (size_t)TOTAL) ? 1 : 0;

    const int T = 256;
    pass1_kernel<<<(TOTAL + T - 1) / T, T>>>(depth, opac, conf, poses);
    pass3_kernel<<<(TOTAL + T - 1) / T, T>>>(depth, cov, rot, opac, sh, conf,
                                             poses, out, write_sel, featN);
    cleanup_kernel<<<CLEAN_BLOCKS, T>>>();
}

// round 10
// speedup vs baseline: 1.1595x; 1.1595x over previous
#include <cuda_runtime.h>
#include <math.h>
#include <stdint.h>

#ifndef M_PI
#define M_PI 3.14159265358979323846
#endif

// Problem shape (fixed by setup_inputs)
#define BB 2
#define NV 4
#define HH 256
#define WW 512
#define HWSZ (HH * WW)            // 131072
#define PP (NV * HWSZ)            // 524288 points per batch
#define TOTAL (BB * PP)           // 1048576 points total
#define NCH 24

#define VOXEL_SIZE 0.1f
#define CONF_W 0.7f
#define OPAC_W 0.3f
#define CONF_THRESH 0.1f
#define OPAC_THRESH 0.01f

#define TABLE_BITS 21
#define TABLE_SIZE (1u << TABLE_BITS)
#define TABLE_MASK (TABLE_SIZE - 1u)
#define INV_SLOT 0xFFFFFFFFu

// Block-local hash size (256 points/block -> <=256 distinct keys)
#define SHASH 512
#define SHMASK (SHASH - 1)

// Scratch (no runtime allocation -> __device__ globals, ZERO-INITIALIZED at
// module load; the cleanup kernel restores the zero state after every launch,
// so each graph replay starts clean). Empty key encoding is 0; real keys
// always have bit 31 set.
__device__ unsigned int  g_keys[TABLE_SIZE];        // 8 MB, 0 = empty
__device__ ulonglong2    g_pair[TABLE_SIZE];        // 32 MB: {max1, max2}
__device__ unsigned int  g_slot[TOTAL];             // 4 MB
__device__ unsigned int  g_used[TOTAL];             // claimed slot list
__device__ unsigned int  g_cnt;                     // #claimed slots
__device__ unsigned int  g_done;                    // cleanup block counter

// ---------------------------------------------------------------------------

// Find (or claim) the GLOBAL table slot for voxel `key` (key != 0 guaranteed).
// On first claim of a slot, record it for post-run cleanup.
__device__ __forceinline__ unsigned probe_slot(unsigned key) {
    unsigned h = (key * 2654435761u) >> (32 - TABLE_BITS);
    for (;;) {
        unsigned cur = g_keys[h];
        if (cur == key) return h;
        if (cur == 0u) {
            unsigned prev = atomicCAS(&g_keys[h], 0u, key);
            if (prev == 0u) {                       // we claimed it: record
                unsigned idx = atomicAdd(&g_cnt, 1u);
                g_used[idx] = h;
                return h;
            }
            if (prev == key) return h;
        }
        h = (h + 1u) & TABLE_MASK;
    }
}

// Packed (score, index) key — ONE definition so pass1/pass3 agree bit-exactly.
__device__ __forceinline__ unsigned long long pack_key(float c, float o,
                                                       unsigned p) {
    float score = __fmaf_rn(CONF_W, c, __fmul_rn(OPAC_W, o));
    return ((unsigned long long)__float_as_uint(score) << 32)
         | (unsigned long long)(0xFFFFFFFFu - p);
}

// Identical arithmetic to the R6 passing kernel (proven numerics).
__device__ __forceinline__ void compute_point(
    int g, const float* __restrict__ depth, const float* __restrict__ opac,
    const float* __restrict__ conf, const float* __restrict__ poses,
    bool& valid, unsigned& key, unsigned long long& packed,
    float& mx, float& my, float& mz)
{
    int b  = g / PP;
    int p  = g - b * PP;
    int n  = p / HWSZ;
    int hw = p - n * HWSZ;
    int h  = hw / WW;
    int w  = hw - h * WW;

    float d = depth[g];
    float c = conf[g];
    float o = opac[g];
    valid = (c > CONF_THRESH) && (o > OPAC_THRESH);

    const float fx = (float)((double)WW / (2.0 * M_PI));
    const float fy = (float)(-(double)HH / M_PI);
    float lon = ((float)w + 0.5f - (float)(WW / 2)) / fx;
    float lat = ((float)h + 0.5f - (float)(HH / 2)) / fy;
    float slat, clat, slon, clon;
    sincosf(lat, &slat, &clat);
    sincosf(lon, &slon, &clon);
    float dx = clat * slon;
    float dy = -slat;
    float dz = clat * clon;

    float px = d * dx, py = d * dy, pz = d * dz;

    const float* M = poses + (size_t)(b * NV + n) * 16;
    mx = M[0] * px + M[1] * py + M[2]  * pz + M[3];
    my = M[4] * px + M[5] * py + M[6]  * pz + M[7];
    mz = M[8] * px + M[9] * py + M[10] * pz + M[11];

    int vx = min(max((int)floorf(mx / VOXEL_SIZE) + 512, 0), 1023);
    int vy = min(max((int)floorf(my / VOXEL_SIZE) + 512, 0), 1023);
    int vz = min(max((int)floorf(mz / VOXEL_SIZE) + 512, 0), 1023);
    unsigned vid = ((unsigned)vx << 20) | ((unsigned)vy << 10) | (unsigned)vz;
    // bit 31 forced -> key is never 0 (0 means empty slot)
    key = 0x80000000u | ((unsigned)b << 30) | vid;

    packed = pack_key(c, o, (unsigned)p);
}

// Block-local aggregation: points first combine into a 512-slot smem hash
// (cheap ATOMS), then only the ~30-60 distinct voxels per block are flushed
// to the global table (few, fully parallel, high-MLP global atomics).
// Streaming-top-2 invariant (validated bit-exact in R4/R8):
//   max2 receives every value that is ever displaced from / loses to max1,
//   hence ends as the global 2nd max. Composition over two levels preserves it.
__global__ void __launch_bounds__(256) pass1_kernel(
    const float* __restrict__ depth, const float* __restrict__ opac,
    const float* __restrict__ conf,  const float* __restrict__ poses)
{
    __shared__ unsigned            sh_key[SHASH];
    __shared__ unsigned long long  sh_m1[SHASH];
    __shared__ unsigned long long  sh_m2[SHASH];
    __shared__ unsigned            sh_gslot[SHASH];
    __shared__ unsigned short      sh_list[SHASH];
    __shared__ unsigned            sh_cnt;

    int tid = threadIdx.x;
    if (tid == 0) sh_cnt = 0u;
#pragma unroll
    for (int i = 0; i < SHASH / 256; i++) {
        sh_key[tid + i * 256] = 0u;
        sh_m1[tid + i * 256] = 0ull;
        sh_m2[tid + i * 256] = 0ull;
    }
    __syncthreads();

    int g = blockIdx.x * 256 + tid;                 // grid exact: TOTAL/256

    bool valid; unsigned key; unsigned long long pk;
    float mx, my, mz;
    compute_point(g, depth, opac, conf, poses, valid, key, pk, mx, my, mz);

    unsigned myslot = 0xFFFFFFFFu;
    if (valid) {
        unsigned h = (key * 2654435761u) >> 23;     // top 9 bits -> [0,512)
        for (;;) {
            unsigned cur = sh_key[h];
            if (cur == key) break;
            if (cur == 0u) {
                unsigned prev = atomicCAS(&sh_key[h], 0u, key);
                if (prev == 0u) {
                    unsigned idx = atomicAdd(&sh_cnt, 1u);
                    sh_list[idx] = (unsigned short)h;
                    break;
                }
                if (prev == key) break;
            }
            h = (h + 1u) & SHMASK;
        }
        myslot = h;
        unsigned long long old = atomicMax(&sh_m1[h], pk);
        unsigned long long v = (pk < old) ? pk : old;
        if (v != 0ull)
            atomicMax(&sh_m2[h], v);
    }
    __syncthreads();

    // Flush distinct voxels to the global table (parallel across threads).
    unsigned cnt = sh_cnt;
    for (unsigned i = tid; i < cnt; i += 256) {
        unsigned h = sh_list[i];
        unsigned k2 = sh_key[h];
        unsigned gslot = probe_slot(k2);
        sh_gslot[h] = gslot;
        unsigned long long top1 = sh_m1[h];
        unsigned long long top2 = sh_m2[h];
        unsigned long long* m1 =
            &reinterpret_cast<unsigned long long*>(g_pair)[2 * (size_t)gslot];
        unsigned long long old = atomicMax(m1, top1);
        unsigned long long d1 = (top1 < old) ? top1 : old;   // displaced
        unsigned long long m = (d1 > top2) ? d1 : top2;
        if (m != 0ull)
            atomicMax(m1 + 1, m);                   // result unused -> RED
    }
    __syncthreads();

    g_slot[g] = (myslot == 0xFFFFFFFFu) ? INV_SLOT : sh_gslot[myslot];
}

__global__ void __launch_bounds__(256) pass3_kernel(
    const float* __restrict__ depth, const float* __restrict__ cov,
    const float* __restrict__ rot,   const float* __restrict__ opac,
    const float* __restrict__ sh,    const float* __restrict__ conf,
    const float* __restrict__ poses, float* __restrict__ out,
    int write_sel, size_t sel_off)
{
    int g = blockIdx.x * blockDim.x + threadIdx.x;
    if (g >= TOTAL) return;

    bool valid; unsigned key; unsigned long long packed;
    float mx, my, mz;
    compute_point(g, depth, opac, conf, poses, valid, key, packed, mx, my, mz);

    float s = 0.0f;
    unsigned slot = g_slot[g];
    if (slot != INV_SLOT) {
        ulonglong2 pr = __ldg(&g_pair[slot]);       // one 16B read for both
        if (packed == pr.x || packed == pr.y) s = 1.0f;
    }

    int b  = g / PP;
    int p  = g - b * PP;
    int n  = p / HWSZ;
    int hw = p - n * HWSZ;

    size_t bn     = (size_t)(b * NV + n);
    size_t base_c = (bn * 3)  * HWSZ + hw;
    size_t base_r = (bn * 4)  * HWSZ + hw;
    size_t base_s = (bn * 12) * HWSZ + hw;

    float f[NCH];
    f[0] = mx; f[1] = my; f[2] = mz;
    f[3] = __ldcs(&cov[base_c]);
    f[4] = __ldcs(&cov[base_c + HWSZ]);
    f[5] = __ldcs(&cov[base_c + 2 * (size_t)HWSZ]);
#pragma unroll
    for (int i = 0; i < 4; i++)
        f[6 + i] = __ldcs(&rot[base_r + (size_t)i * HWSZ]);
    f[10] = opac[g];
#pragma unroll
    for (int i = 0; i < 12; i++)
        f[11 + i] = __ldcs(&sh[base_s + (size_t)i * HWSZ]);
    f[23] = conf[g];

#pragma unroll
    for (int i = 0; i < NCH; i++) f[i] *= s;

    float4* dst = reinterpret_cast<float4*>(out + (size_t)g * NCH);
#pragma unroll
    for (int i = 0; i < 6; i++)
        __stcs(dst + i, make_float4(f[4*i], f[4*i+1], f[4*i+2], f[4*i+3]));

    if (write_sel)
        __stcs(out + sel_off + (size_t)g, s);
}

// Zero only the slots that were claimed this launch; restores the pristine
// zero state so the next replay starts clean. Last block resets the counters.
#define CLEAN_BLOCKS 512
__global__ void __launch_bounds__(256) cleanup_kernel() {
    unsigned cnt = *(volatile unsigned*)&g_cnt;
    unsigned stride = CLEAN_BLOCKS * 256;
    for (unsigned i = blockIdx.x * 256 + threadIdx.x; i < cnt; i += stride) {
        unsigned slot = g_used[i];
        g_keys[slot] = 0u;
        ulonglong2 z; z.x = 0ull; z.y = 0ull;
        g_pair[slot] = z;
    }
    __threadfence();
    if (threadIdx.x == 0) {
        unsigned done = atomicAdd(&g_done, 1u);
        if (done == CLEAN_BLOCKS - 1) {
            g_cnt = 0u;
            g_done = 0u;
            __threadfence();
        }
    }
}

// ---------------------------------------------------------------------------

extern "C" void kernel_launch(void* const* d_in, const int* in_sizes, int n_in,
                              void* d_out, int out_size) {
    const float* depth = (const float*)d_in[0];
    const float* cov   = (const float*)d_in[1];
    const float* rot   = (const float*)d_in[2];
    const float* opac  = (const float*)d_in[3];
    const float* sh    = (const float*)d_in[4];
    const float* conf  = (const float*)d_in[5];
    const float* poses = (const float*)d_in[6];
    float* out = (float*)d_out;

    size_t featN = (size_t)TOTAL * NCH;
    int write_sel = ((size_t)out_size >= featN + (size_t)TOTAL) ? 1 : 0;

    const int T = 256;
    pass1_kernel<<<TOTAL / T, T>>>(depth, opac, conf, poses);
    pass3_kernel<<<(TOTAL + T - 1) / T, T>>>(depth, cov, rot, opac, sh, conf,
                                             poses, out, write_sel, featN);
    cleanup_kernel<<<CLEAN_BLOCKS, T>>>();
}